// round 13
// baseline (speedup 1.0000x reference)
#include <cuda_runtime.h>
#include <cuda_bf16.h>
#include <cstdint>
#include <cstddef>

#define BB 8
#define TT 512
#define HH 512
#define PP 20
#define VV 32000
#define BT (BB*TT)     /* 4096 */
#define G4H (4*HH)     /* 2048 */
#define G4P (4*PP)     /* 80   */

// ------------------------- scratch (no runtime alloc allowed; 16B-aligned) -------------------
__device__ __align__(16) float g_embA[BT*HH];
__device__ __align__(16) float g_xg_enc[(size_t)BT*G4H];
__device__ __align__(16) float g_enc[BT*HH];
__device__ __align__(16) float g_hbuf[2*BB*HH];
__device__ __align__(16) float g_xg_pos[BT*G4P];
__device__ __align__(16) float g_mu[BT];
__device__ __align__(16) float g_sg[BT];
__device__ __align__(16) float g_gw[(size_t)BB*TT*TT];
__device__ __align__(16) float g_cat[(size_t)BT*2*HH];        // [ctx | enc]
__device__ __align__(16) float g_comb[BT*HH];
__device__ __align__(16) float g_bias_enc[G4H];
__device__ __align__(16) float g_bias_pos[G4P];
__device__ unsigned g_bar;
// split-bf16 operands for HMMA GEMMs
__device__ __align__(16) __nv_bfloat16 g_embA_hi[BT*HH];
__device__ __align__(16) __nv_bfloat16 g_embA_lo[BT*HH];
__device__ __align__(16) __nv_bfloat16 g_wih_hi[G4H*HH];
__device__ __align__(16) __nv_bfloat16 g_wih_lo[G4H*HH];
__device__ __align__(16) __nv_bfloat16 g_cat_hi[(size_t)BT*2*HH];
__device__ __align__(16) __nv_bfloat16 g_cat_lo[(size_t)BT*2*HH];
__device__ __align__(16) __nv_bfloat16 g_wcat_hi[HH*2*HH];
__device__ __align__(16) __nv_bfloat16 g_wcat_lo[HH*2*HH];
__device__ __align__(16) __nv_bfloat16 g_comb_hi[BT*HH];
__device__ __align__(16) __nv_bfloat16 g_comb_lo[BT*HH];
__device__ __align__(16) __nv_bfloat16 g_emb_hi[(size_t)VV*HH];
__device__ __align__(16) __nv_bfloat16 g_emb_lo[(size_t)VV*HH];

__device__ __forceinline__ float sigf(float x) { return 1.f / (1.f + expf(-x)); }

#define FMA2(acc, a, b) asm("fma.rn.f32x2 %0, %1, %2, %0;" : "+l"(acc) : "l"(a), "l"(b))

// mma.sync m16n8k16 bf16 (baseline PTX, sm_80+ — NO arch-'a' features; harness targets sm_103)
#define MMA_BF16(c, a, b0, b1)                                              \
    asm volatile("mma.sync.aligned.m16n8k16.row.col.f32.bf16.bf16.f32 "     \
        "{%0,%1,%2,%3}, {%4,%5,%6,%7}, {%8,%9}, {%0,%1,%2,%3};"             \
        : "+f"((c)[0]), "+f"((c)[1]), "+f"((c)[2]), "+f"((c)[3])            \
        : "r"((a)[0]), "r"((a)[1]), "r"((a)[2]), "r"((a)[3]),               \
          "r"(b0), "r"(b1))

// cp.async (baseline PTX, sm_80+)
#define CP_ASYNC16(saddr, gptr)                                             \
    asm volatile("cp.async.cg.shared.global [%0], [%1], 16;"                \
        :: "r"(saddr), "l"(gptr) : "memory")
#define CP_COMMIT() asm volatile("cp.async.commit_group;" ::: "memory")
#define CP_WAIT1()  asm volatile("cp.async.wait_group 1;" ::: "memory")
#define CP_WAIT0()  asm volatile("cp.async.wait_group 0;" ::: "memory")

// ------------------------- reset (per replay: barrier + h0) -------------------------
__global__ void reset_kernel() {
    int i = blockIdx.x * blockDim.x + threadIdx.x;
    if (i == 0) g_bar = 0u;
    if (i < BB * HH) g_hbuf[i] = 0.f;
}

// ------------------------- combined biases -------------------------
__global__ void bias_kernel(const float* __restrict__ bih, const float* __restrict__ bhh,
                            const float* __restrict__ pbih, const float* __restrict__ pbhh) {
    int i = blockIdx.x * blockDim.x + threadIdx.x;
    if (i < G4H) g_bias_enc[i] = bih[i] + bhh[i];
    if (i < G4P) g_bias_pos[i] = pbih[i] + pbhh[i];
}

// ------------------------- embedding gather -------------------------
__global__ void gather_kernel(const int* __restrict__ tokens, const float* __restrict__ emb) {
    int i = blockIdx.x * blockDim.x + threadIdx.x;      // float4 index
    if (i >= BT * (HH / 4)) return;
    int r = i >> 7;
    int c4 = i & 127;
    int tok = tokens[r];
    ((float4*)g_embA)[i] = ((const float4*)(emb + (size_t)tok * HH))[c4];
}

// ------------------------- enc -> g_cat[:, HH:2HH] copy -------------------------
__global__ void enccat_kernel() {
    int i = blockIdx.x * blockDim.x + threadIdx.x;      // float4 index over BT*HH/4
    if (i >= BT * (HH / 4)) return;
    int row = i >> 7, c4 = i & 127;
    ((float4*)g_cat)[(size_t)row * (2 * HH / 4) + (HH / 4) + c4] = ((const float4*)g_enc)[i];
}

// ------------------------- fp32 -> split bf16 (hi/lo) -------------------------
__global__ void split_kernel(const float* __restrict__ src, __nv_bfloat16* __restrict__ hi,
                             __nv_bfloat16* __restrict__ lo, long long n) {
    long long i = (long long)blockIdx.x * blockDim.x + threadIdx.x;
    if (i >= n) return;
    float x = src[i];
    __nv_bfloat16 h = __float2bfloat16(x);
    float r = x - __bfloat162float(h);
    hi[i] = h;
    lo[i] = __float2bfloat16(r);
}

// ------------------------- fp32 SGEMM, double-buffered, f32x2-packed FMA -------------------------
// C = A[M,K] * op(B) (+bias). Used only for ctx (non-trans) and xg_pos (N=80).
template <bool TRANSB>
__global__ void __launch_bounds__(256)
sgemm_kernel(const float* __restrict__ A, int lda, long long sA,
             const float* __restrict__ B, int ldb, long long sB,
             float* __restrict__ C, int ldc, long long sC,
             int M, int N, int K,
             const float* __restrict__ bias, int act, float beta) {
    constexpr int BM = 128, BN = 128, BK = 8;
    __shared__ float As[2][BK][BM + 4];
    __shared__ float Bs[2][BK][BN + 4];

    A += (size_t)blockIdx.z * sA;
    B += (size_t)blockIdx.z * sB;
    C += (size_t)blockIdx.z * sC;

    const int bRow = blockIdx.y * BM;
    const int bCol = blockIdx.x * BN;
    const int tid = threadIdx.x;

    const int aRow = tid >> 1, aK = (tid & 1) * 4;
    const int tRow = (tid / 16) * 8, tCol = (tid % 16) * 8;
    const int bN  = tid >> 1, bKk = (tid & 1) * 4;
    const int bKr = tid >> 5, bN4 = (tid & 31) * 4;

    unsigned long long acc2[8][4];
#pragma unroll
    for (int i = 0; i < 8; i++)
#pragma unroll
        for (int j2 = 0; j2 < 4; j2++) acc2[i][j2] = 0ull;

    auto fetchA = [&](int kt) {
        return *(const float4*)(A + (size_t)(bRow + aRow) * lda + kt + aK);
    };
    auto fetchB = [&](int kt) {
        float4 bv = make_float4(0.f, 0.f, 0.f, 0.f);
        if (TRANSB) {
            if (bCol + bN < N)
                bv = *(const float4*)(B + (size_t)(bCol + bN) * ldb + kt + bKk);
        } else {
            if (bCol + bN4 < N)
                bv = *(const float4*)(B + (size_t)(kt + bKr) * ldb + bCol + bN4);
        }
        return bv;
    };
    auto commit = [&](int buf, float4 av, float4 bv) {
        As[buf][aK + 0][aRow] = av.x; As[buf][aK + 1][aRow] = av.y;
        As[buf][aK + 2][aRow] = av.z; As[buf][aK + 3][aRow] = av.w;
        if (TRANSB) {
            Bs[buf][bKk + 0][bN] = bv.x; Bs[buf][bKk + 1][bN] = bv.y;
            Bs[buf][bKk + 2][bN] = bv.z; Bs[buf][bKk + 3][bN] = bv.w;
        } else {
            Bs[buf][bKr][bN4 + 0] = bv.x; Bs[buf][bKr][bN4 + 1] = bv.y;
            Bs[buf][bKr][bN4 + 2] = bv.z; Bs[buf][bKr][bN4 + 3] = bv.w;
        }
    };

    {
        float4 av = fetchA(0), bv = fetchB(0);
        commit(0, av, bv);
    }
    __syncthreads();

    const int nTiles = K / BK;
    int buf = 0;
    for (int tile = 0; tile < nTiles; tile++) {
        float4 av, bv;
        if (tile + 1 < nTiles) {
            av = fetchA((tile + 1) * BK);
            bv = fetchB((tile + 1) * BK);
        }
#pragma unroll
        for (int kk = 0; kk < BK; kk++) {
            float4 ra0 = *(const float4*)&As[buf][kk][tRow];
            float4 ra1 = *(const float4*)&As[buf][kk][tRow + 4];
            float ra[8] = {ra0.x, ra0.y, ra0.z, ra0.w, ra1.x, ra1.y, ra1.z, ra1.w};
            unsigned long long apair[8];
#pragma unroll
            for (int i = 0; i < 8; i++)
                asm("mov.b64 %0, {%1, %1};" : "=l"(apair[i]) : "f"(ra[i]));
            const unsigned long long* bp =
                (const unsigned long long*)&Bs[buf][kk][tCol];
            unsigned long long bpair[4];
#pragma unroll
            for (int j2 = 0; j2 < 4; j2++) bpair[j2] = bp[j2];
#pragma unroll
            for (int i = 0; i < 8; i++)
#pragma unroll
                for (int j2 = 0; j2 < 4; j2++)
                    FMA2(acc2[i][j2], apair[i], bpair[j2]);
        }
        if (tile + 1 < nTiles) {
            commit(buf ^ 1, av, bv);
            __syncthreads();
            buf ^= 1;
        }
    }

    float acc[8][8];
#pragma unroll
    for (int i = 0; i < 8; i++)
#pragma unroll
        for (int j2 = 0; j2 < 4; j2++)
            asm("mov.b64 {%0, %1}, %2;"
                : "=f"(acc[i][2 * j2]), "=f"(acc[i][2 * j2 + 1])
                : "l"(acc2[i][j2]));

    const bool fullTile = (bCol + BN <= N);
    if (fullTile && beta == 0.f && act == 0) {
#pragma unroll
        for (int i = 0; i < 8; i++) {
            size_t rowOff = (size_t)(bRow + tRow + i) * ldc + bCol + tCol;
#pragma unroll
            for (int j4 = 0; j4 < 2; j4++) {
                float4 v = make_float4(acc[i][j4 * 4 + 0], acc[i][j4 * 4 + 1],
                                       acc[i][j4 * 4 + 2], acc[i][j4 * 4 + 3]);
                if (bias) {
                    int col = bCol + tCol + j4 * 4;
                    v.x += bias[col + 0]; v.y += bias[col + 1];
                    v.z += bias[col + 2]; v.w += bias[col + 3];
                }
                *(float4*)(C + rowOff + j4 * 4) = v;
            }
        }
    } else {
#pragma unroll
        for (int i = 0; i < 8; i++) {
            int row = bRow + tRow + i;
#pragma unroll
            for (int j = 0; j < 8; j++) {
                int col = bCol + tCol + j;
                if (col < N) {
                    float v = acc[i][j];
                    if (beta != 0.f) v += beta * C[(size_t)row * ldc + col];
                    if (bias) v += bias[col];
                    if (act == 1) v = tanhf(v);
                    C[(size_t)row * ldc + col] = v;
                }
            }
        }
    }
}

// ------------------------- HMMA split-bf16 GEMM (mma.sync m16n8k16, cp.async pipelined) -----
// out[M, N] = A @ B^T (+bias)(tanh) via Ah*Bh + Ah*Bl + Al*Bh (fp32 accum).
// A: [M, K] bf16 hi/lo row-major (lda=K). B: [N, K] bf16 hi/lo row-major (ldb=K)
//   -> B is exactly the .col (k-major) operand layout of mma.sync.
// Block 128x128, BK=32, 256 thr = 8 warps, warp tile 32(M) x 64(N).
// 2-stage cp.async pipeline: chunk c+1 streams into stage^1 while MMA runs on stage.
// Dynamic smem: 2 stages x 4 tiles x 128 x MM_LDS bf16 = 80 KB; 2 CTAs/SM.
// Requires: M,N multiples of 128; K multiple of 32; bias non-null.
#define MM_LDS 40   /* 32 + 8 pad bf16; frag-LDS bank = (20g+t4)%32, all 32 distinct */
#define MM_TILE (128 * MM_LDS)          /* bf16 per tile  */
#define MM_STAGE (4 * MM_TILE)          /* bf16 per stage */
#define SMEM_MM (2 * MM_STAGE * 2)      /* bytes          */

__device__ __forceinline__ void mm_load_async(uint32_t dst, const __nv_bfloat16* src,
                                              int row0, int col0, int ld, int tid) {
    // 128 rows x 32 bf16 = 512 x 16B chunks; 2 per thread
#pragma unroll
    for (int it = 0; it < 2; it++) {
        int idx = tid + it * 256;
        int r = idx >> 2, c4 = idx & 3;
        const __nv_bfloat16* g = src + (size_t)(row0 + r) * ld + col0 + c4 * 8;
        CP_ASYNC16(dst + (uint32_t)(r * MM_LDS + c4 * 8) * 2, g);
    }
}

__global__ void __launch_bounds__(256, 2)
mma_gemm_kernel(const __nv_bfloat16* __restrict__ Ah, const __nv_bfloat16* __restrict__ Al,
                const __nv_bfloat16* __restrict__ Bh, const __nv_bfloat16* __restrict__ Bl,
                int K, const float* __restrict__ bias, int act,
                float* __restrict__ out, int ldc) {
    extern __shared__ __nv_bfloat16 dyn[];
    const uint32_t sbase = (uint32_t)__cvta_generic_to_shared(dyn);

    const int tid = threadIdx.x;
    const int w = tid >> 5, lane = tid & 31;
    const int g = lane >> 2, t4 = lane & 3;
    const int wm = w & 3, wn = w >> 2;           // 4 M-warps x 2 N-warps
    const int n0 = blockIdx.x * 128, m0 = blockIdx.y * 128;

    float acc[2][8][4];
#pragma unroll
    for (int mt = 0; mt < 2; mt++)
#pragma unroll
        for (int nt = 0; nt < 8; nt++)
#pragma unroll
            for (int q = 0; q < 4; q++) acc[mt][nt][q] = 0.f;

    auto issue_chunk = [&](int kc, int st) {
        uint32_t sb = sbase + (uint32_t)(st * MM_STAGE) * 2;
        mm_load_async(sb + 0u * MM_TILE * 2, Ah, m0, kc, K, tid);
        mm_load_async(sb + 1u * MM_TILE * 2, Al, m0, kc, K, tid);
        mm_load_async(sb + 2u * MM_TILE * 2, Bh, n0, kc, K, tid);
        mm_load_async(sb + 3u * MM_TILE * 2, Bl, n0, kc, K, tid);
        CP_COMMIT();
    };

    const int nChunks = K / 32;
    issue_chunk(0, 0);

    for (int c = 0; c < nChunks; c++) {
        const int st = c & 1;
        if (c + 1 < nChunks) {
            issue_chunk((c + 1) * 32, st ^ 1);
            CP_WAIT1();                 // chunk c landed; chunk c+1 may be in flight
        } else {
            CP_WAIT0();
        }
        __syncthreads();

        const __nv_bfloat16* sAh = dyn + st * MM_STAGE + 0 * MM_TILE;
        const __nv_bfloat16* sAl = dyn + st * MM_STAGE + 1 * MM_TILE;
        const __nv_bfloat16* sBh = dyn + st * MM_STAGE + 2 * MM_TILE;
        const __nv_bfloat16* sBl = dyn + st * MM_STAGE + 3 * MM_TILE;
#pragma unroll
        for (int ks = 0; ks < 2; ks++) {
            const int kb = ks * 16 + t4 * 2;
            uint32_t ahf[2][4], alf[2][4];
#pragma unroll
            for (int mt = 0; mt < 2; mt++) {
                int r0 = (wm * 32 + mt * 16 + g) * MM_LDS + kb;
                ahf[mt][0] = *(const uint32_t*)&sAh[r0];
                ahf[mt][1] = *(const uint32_t*)&sAh[r0 + 8 * MM_LDS];
                ahf[mt][2] = *(const uint32_t*)&sAh[r0 + 8];
                ahf[mt][3] = *(const uint32_t*)&sAh[r0 + 8 * MM_LDS + 8];
                alf[mt][0] = *(const uint32_t*)&sAl[r0];
                alf[mt][1] = *(const uint32_t*)&sAl[r0 + 8 * MM_LDS];
                alf[mt][2] = *(const uint32_t*)&sAl[r0 + 8];
                alf[mt][3] = *(const uint32_t*)&sAl[r0 + 8 * MM_LDS + 8];
            }
#pragma unroll
            for (int nt = 0; nt < 8; nt++) {
                int nr = (wn * 64 + nt * 8 + g) * MM_LDS + kb;
                uint32_t bh0 = *(const uint32_t*)&sBh[nr];
                uint32_t bh1 = *(const uint32_t*)&sBh[nr + 8];
                uint32_t bl0 = *(const uint32_t*)&sBl[nr];
                uint32_t bl1 = *(const uint32_t*)&sBl[nr + 8];
#pragma unroll
                for (int mt = 0; mt < 2; mt++) {
                    MMA_BF16(acc[mt][nt], ahf[mt], bh0, bh1);
                    MMA_BF16(acc[mt][nt], ahf[mt], bl0, bl1);
                    MMA_BF16(acc[mt][nt], alf[mt], bh0, bh1);
                }
            }
        }
        __syncthreads();   // all reads of stage st done before it is refilled (c+2)
    }

    // epilogue: c0,c1 -> (row, col..col+1); c2,c3 -> (row+8, col..col+1)
#pragma unroll
    for (int mt = 0; mt < 2; mt++) {
#pragma unroll
        for (int nt = 0; nt < 8; nt++) {
            int row = m0 + wm * 32 + mt * 16 + g;
            int col = n0 + wn * 64 + nt * 8 + t4 * 2;
            float b0 = bias[col], b1 = bias[col + 1];
            float v0 = acc[mt][nt][0] + b0, v1 = acc[mt][nt][1] + b1;
            float v2 = acc[mt][nt][2] + b0, v3 = acc[mt][nt][3] + b1;
            if (act == 1) {
                v0 = tanhf(v0); v1 = tanhf(v1);
                v2 = tanhf(v2); v3 = tanhf(v3);
            }
            *(float2*)(out + (size_t)row * ldc + col) = make_float2(v0, v1);
            *(float2*)(out + (size_t)(row + 8) * ldc + col) = make_float2(v2, v3);
        }
    }
}

// ------------------------- persistent encoder LSTM (register-stationary weights) -----------
// 128 blocks x 128 threads. Block owns 4 hidden units (16 gate rows).
// Thread (r = tid>>3 in [0,16), ks = tid&7): gate row r, k-slice [ks*64, ks*64+64).
// Weights live in registers (32 f32x2 pairs, loaded once). Only h goes through smem.
// h_sm layout: [b][ks*68 + j] (68-float slice pad -> conflict-free stride-256B reads).
__global__ void __launch_bounds__(128)
enc_lstm_kernel(const float* __restrict__ Whh) {
    __shared__ float h_sm[8 * 544];
    __shared__ float part_sm[16 * 64];
    __shared__ float gate_sm[128];

    const int tid = threadIdx.x;
    const int r  = tid >> 3;
    const int ks = tid & 7;
    const int k0 = blockIdx.x * 4;
    const int jg = (r >> 2) * HH + k0 + (r & 3);

    unsigned long long wreg[32];
    {
        const ulonglong2* wr = (const ulonglong2*)(Whh + (size_t)jg * HH + ks * 64);
#pragma unroll
        for (int m = 0; m < 16; m++) {
            ulonglong2 v = wr[m];
            wreg[2 * m] = v.x; wreg[2 * m + 1] = v.y;
        }
    }
    const ulonglong2* hptr[8];
#pragma unroll
    for (int b = 0; b < 8; b++)
        hptr[b] = (const ulonglong2*)&h_sm[b * 544 + ks * 68];

    float c = 0.f;

    for (int t = 0; t < TT; t++) {
        const int cur = t & 1;
        const float4* hg = (const float4*)(g_hbuf + cur * (BB * HH));
        for (int i = tid; i < BB * HH / 4; i += 128) {
            float4 v = __ldcg(hg + i);
            int bb = i >> 7, k4 = i & 127;
            *(float4*)&h_sm[bb * 544 + (k4 >> 4) * 68 + (k4 & 15) * 4] = v;
        }
        float xgv = __ldg(&g_xg_enc[(size_t)(ks * TT + t) * G4H + jg]);
        __syncthreads();

        unsigned long long acc[8];
#pragma unroll
        for (int b = 0; b < 8; b++) acc[b] = 0ull;
#pragma unroll
        for (int m = 0; m < 16; m++) {
            ulonglong2 hv[8];
#pragma unroll
            for (int b = 0; b < 8; b++) hv[b] = hptr[b][m];
#pragma unroll
            for (int b = 0; b < 8; b++) FMA2(acc[b], wreg[2 * m], hv[b].x);
#pragma unroll
            for (int b = 0; b < 8; b++) FMA2(acc[b], wreg[2 * m + 1], hv[b].y);
        }
#pragma unroll
        for (int b = 0; b < 8; b++) {
            float lo, hi;
            asm("mov.b64 {%0, %1}, %2;" : "=f"(lo), "=f"(hi) : "l"(acc[b]));
            part_sm[r * 64 + b * 8 + ks] = lo + hi;
        }
        __syncthreads();

        {
            float s = xgv;
            const float* pp = &part_sm[r * 64 + ks * 8];
#pragma unroll
            for (int q = 0; q < 8; q++) s += pp[q];
            gate_sm[r * 8 + ks] = s;
        }
        __syncthreads();

        if (tid < 32) {
            int kl = tid >> 3, b2 = tid & 7;
            float iv = gate_sm[(0 + kl) * 8 + b2];
            float fv = gate_sm[(4 + kl) * 8 + b2];
            float gv = gate_sm[(8 + kl) * 8 + b2];
            float ov = gate_sm[(12 + kl) * 8 + b2];
            c = sigf(fv) * c + sigf(iv) * tanhf(gv);
            float h = sigf(ov) * tanhf(c);
            int nxt = cur ^ 1;
            g_hbuf[nxt * (BB * HH) + b2 * HH + k0 + kl] = h;
            g_enc[(size_t)(b2 * TT + t) * HH + k0 + kl] = h;
            __threadfence();
        }
        __syncthreads();
        if (tid == 0) {
            __threadfence();
            atomicAdd(&g_bar, 1u);
            unsigned tgt = (unsigned)(t + 1) * gridDim.x;
            volatile unsigned* vb = &g_bar;
            while (*vb < tgt) { }
        }
        __syncthreads();
    }
}

// ------------------------- positional LSTM + mu/sg scan (one block per batch) -------------------------
__global__ void __launch_bounds__(128)
pos_lstm_kernel(const float* __restrict__ Whh, const float* __restrict__ W_mu,
                const float* __restrict__ b_mu, const float* __restrict__ W_sig,
                const float* __restrict__ b_sig, const int* __restrict__ pad_lengths) {
    __shared__ float wp[G4P * PP];
    __shared__ float hp[PP];
    __shared__ float gate_sm[G4P];
    __shared__ float mwsg[4];

    const int b = blockIdx.x;
    const int tid = threadIdx.x;
    const float L = (float)pad_lengths[b];

    for (int i = tid; i < G4P * PP; i += 128) wp[i] = Whh[i];
    if (tid < PP) hp[tid] = 0.f;
    float c = 0.f;
    float mu_prev = 0.f;
    __syncthreads();

    for (int t = 0; t < TT; t++) {
        if (tid < G4P) {
            float g = g_xg_pos[(size_t)(b * TT + t) * G4P + tid];
            const float* wr = &wp[tid * PP];
#pragma unroll
            for (int k = 0; k < PP; k++) g += hp[k] * wr[k];
            gate_sm[tid] = g;
        }
        __syncthreads();
        if (tid < PP) {
            float iv = gate_sm[tid], fv = gate_sm[PP + tid];
            float gv = gate_sm[2 * PP + tid], ov = gate_sm[3 * PP + tid];
            c = sigf(fv) * c + sigf(iv) * tanhf(gv);
            float h = sigf(ov) * tanhf(c);
            hp[tid] = h;
        }
        __syncthreads();
        if (tid < 4) {
            float s = 0.f;
            if (tid < 3) {
#pragma unroll
                for (int k = 0; k < PP; k++) s += hp[k] * W_mu[tid * PP + k];
                mwsg[tid] = fmaxf(s + b_mu[tid], 0.f);
            } else {
#pragma unroll
                for (int k = 0; k < PP; k++) s += hp[k] * W_sig[k];
                float sgv = sigf(s + b_sig[0]);
                mwsg[3] = sgv;
                g_sg[b * TT + t] = sgv;
            }
        }
        __syncthreads();
        if (tid == 0) {
            float tf = (float)t;
            float mu = mwsg[0] * mu_prev + mwsg[1] / L + mwsg[2] * (tf + 1.f) / L;
            mu = fmaxf(mu, tf / L);
            mu_prev = mu;
            g_mu[b * TT + t] = mu;
        }
        __syncthreads();
    }
}

// ------------------------- attention weights (gaussian, causal, L1-normalized) -------------------------
__global__ void __launch_bounds__(128)
attn_w_kernel(const int* __restrict__ pad_lengths) {
    const int tq = blockIdx.x;
    const int b = blockIdx.y;
    const int tid = threadIdx.x;
    __shared__ float red[5];

    const float mu = g_mu[b * TT + tq];
    const float s = g_sg[b * TT + tq];
    const float inv_den = 1.f / (2.f * s * s + 0.001f);
    const float L = (float)pad_lengths[b];

    float e[4];
    float sum = 0.f;
#pragma unroll
    for (int u = 0; u < 4; u++) {
        int tk = tid + u * 128;
        float v = 0.f;
        if (tk <= tq) {
            float d = (float)tk / L - mu;
            v = expf(-d * d * inv_den);
        }
        e[u] = v;
        sum += v;
    }
#pragma unroll
    for (int off = 16; off; off >>= 1) sum += __shfl_down_sync(0xffffffffu, sum, off);
    if ((tid & 31) == 0) red[tid >> 5] = sum;
    __syncthreads();
    if (tid == 0) red[4] = 1.f / fmaxf(red[0] + red[1] + red[2] + red[3], 1e-12f);
    __syncthreads();
    float inv = red[4];
    float* row = &g_gw[((size_t)b * TT + tq) * TT];
#pragma unroll
    for (int u = 0; u < 4; u++) row[tid + u * 128] = e[u] * inv;
}

// ------------------------- host -------------------------
extern "C" void kernel_launch(void* const* d_in, const int* in_sizes, int n_in,
                              void* d_out, int out_size) {
    const int*   tokens      = (const int*)d_in[0];
    const int*   pad_lengths = (const int*)d_in[1];
    const float* embedding   = (const float*)d_in[2];
    const float* enc_Wih     = (const float*)d_in[3];
    const float* enc_Whh     = (const float*)d_in[4];
    const float* enc_bih     = (const float*)d_in[5];
    const float* enc_bhh     = (const float*)d_in[6];
    const float* pos_Wih     = (const float*)d_in[7];
    const float* pos_Whh     = (const float*)d_in[8];
    const float* pos_bih     = (const float*)d_in[9];
    const float* pos_bhh     = (const float*)d_in[10];
    const float* W_mu        = (const float*)d_in[11];
    const float* b_mu        = (const float*)d_in[12];
    const float* W_sig       = (const float*)d_in[13];
    const float* b_sig       = (const float*)d_in[14];
    const float* W_cat       = (const float*)d_in[15];
    const float* b_cat       = (const float*)d_in[16];
    const float* dec_b       = (const float*)d_in[17];
    float* out = (float*)d_out;

    float *p_embA, *p_xg_enc, *p_enc, *p_xg_pos, *p_gw, *p_cat, *p_comb, *p_benc, *p_bpos;
    __nv_bfloat16 *p_eAhi, *p_eAlo, *p_wihhi, *p_wihlo, *p_cathi, *p_catlo;
    __nv_bfloat16 *p_wcathi, *p_wcatlo, *p_chi, *p_clo, *p_ehi, *p_elo;
    cudaGetSymbolAddress((void**)&p_embA,   g_embA);
    cudaGetSymbolAddress((void**)&p_xg_enc, g_xg_enc);
    cudaGetSymbolAddress((void**)&p_enc,    g_enc);
    cudaGetSymbolAddress((void**)&p_xg_pos, g_xg_pos);
    cudaGetSymbolAddress((void**)&p_gw,     g_gw);
    cudaGetSymbolAddress((void**)&p_cat,    g_cat);
    cudaGetSymbolAddress((void**)&p_comb,   g_comb);
    cudaGetSymbolAddress((void**)&p_benc,   g_bias_enc);
    cudaGetSymbolAddress((void**)&p_bpos,   g_bias_pos);
    cudaGetSymbolAddress((void**)&p_eAhi,   g_embA_hi);
    cudaGetSymbolAddress((void**)&p_eAlo,   g_embA_lo);
    cudaGetSymbolAddress((void**)&p_wihhi,  g_wih_hi);
    cudaGetSymbolAddress((void**)&p_wihlo,  g_wih_lo);
    cudaGetSymbolAddress((void**)&p_cathi,  g_cat_hi);
    cudaGetSymbolAddress((void**)&p_catlo,  g_cat_lo);
    cudaGetSymbolAddress((void**)&p_wcathi, g_wcat_hi);
    cudaGetSymbolAddress((void**)&p_wcatlo, g_wcat_lo);
    cudaGetSymbolAddress((void**)&p_chi,    g_comb_hi);
    cudaGetSymbolAddress((void**)&p_clo,    g_comb_lo);
    cudaGetSymbolAddress((void**)&p_ehi,    g_emb_hi);
    cudaGetSymbolAddress((void**)&p_elo,    g_emb_lo);

    cudaFuncSetAttribute(mma_gemm_kernel,
                         cudaFuncAttributeMaxDynamicSharedMemorySize, SMEM_MM);

    auto launch_split = [](const float* s, __nv_bfloat16* h, __nv_bfloat16* l, long long n) {
        split_kernel<<<(unsigned)((n + 255) / 256), 256>>>(s, h, l, n);
    };

    // 1. reset barrier + h0
    reset_kernel<<<16, 256>>>();
    // 2. combined biases
    bias_kernel<<<8, 256>>>(enc_bih, enc_bhh, pos_bih, pos_bhh);
    // 3. embedding gather; splits for HMMA operands
    gather_kernel<<<(BT * (HH / 4) + 255) / 256, 256>>>(tokens, embedding);
    launch_split(embedding, p_ehi, p_elo, (long long)VV * HH);
    launch_split(p_embA, p_eAhi, p_eAlo, (long long)BT * HH);
    launch_split(enc_Wih, p_wihhi, p_wihlo, (long long)G4H * HH);
    launch_split(W_cat, p_wcathi, p_wcatlo, (long long)HH * 2 * HH);
    // 4. xg_enc = embA @ enc_Wih^T + (bih+bhh)  [4096 x 2048], HMMA
    mma_gemm_kernel<<<dim3(G4H / 128, BT / 128, 1), 256, SMEM_MM>>>(
        p_eAhi, p_eAlo, p_wihhi, p_wihlo, HH, p_benc, 0, p_xg_enc, G4H);
    // 5. encoder LSTM (persistent, grid barrier, register-stationary weights)
    enc_lstm_kernel<<<128, 128>>>(enc_Whh);
    // 6. xg_pos = enc @ pos_Wih^T + (pbih+pbhh)  [4096 x 80], fp32 (N=80)
    sgemm_kernel<true><<<dim3(1, BT / 128, 1), 256>>>(
        p_enc, HH, 0, pos_Wih, HH, 0, p_xg_pos, G4P, 0,
        BT, G4P, HH, p_bpos, 0, 0.f);
    // 7. positional LSTM + mu/sg scan
    pos_lstm_kernel<<<BB, 128>>>(pos_Whh, W_mu, b_mu, W_sig, b_sig, pad_lengths);
    // 8. attention weights
    attn_w_kernel<<<dim3(TT, BB, 1), 128>>>(pad_lengths);
    // 9. ctx[b] = g[b] @ enc[b] written into g_cat[:, 0:512] (ldc=1024); enc copy into [:, 512:1024]
    sgemm_kernel<false><<<dim3(HH / 128, TT / 128, BB), 256>>>(
        p_gw, TT, (long long)TT * TT, p_enc, HH, (long long)TT * HH,
        p_cat, 2 * HH, (long long)TT * 2 * HH,
        TT, HH, TT, nullptr, 0, 0.f);
    enccat_kernel<<<(BT * (HH / 4) + 255) / 256, 256>>>();
    // 10+11. comb = tanh([ctx,enc] @ W_cat^T + b_cat)  [4096 x 512], K=1024, HMMA
    launch_split(p_cat, p_cathi, p_catlo, (long long)BT * 2 * HH);
    mma_gemm_kernel<<<dim3(HH / 128, BT / 128, 1), 256, SMEM_MM>>>(
        p_cathi, p_catlo, p_wcathi, p_wcatlo, 2 * HH, b_cat, 1, p_comb, HH);
    // 11b. split comb (decoder A operand)
    launch_split(p_comb, p_chi, p_clo, (long long)BT * HH);
    // 12. logits = comb @ embedding^T + dec_b  [4096 x 32000], HMMA
    mma_gemm_kernel<<<dim3(VV / 128, BT / 128, 1), 256, SMEM_MM>>>(
        p_chi, p_clo, p_ehi, p_elo, HH, dec_b, 0, out, VV);

    (void)in_sizes; (void)n_in; (void)out_size;
}

// round 14
// speedup vs baseline: 1.0807x; 1.0807x over previous
#include <cuda_runtime.h>
#include <cuda_fp16.h>
#include <cstdint>
#include <cstddef>

#define BB 8
#define TT 512
#define HH 512
#define PP 20
#define VV 32000
#define BT (BB*TT)     /* 4096 */
#define G4H (4*HH)     /* 2048 */
#define G4P (4*PP)     /* 80   */

// ------------------------- scratch (no runtime alloc allowed; 16B-aligned) -------------------
__device__ __align__(16) float g_xg_enc[(size_t)BT*G4H];
__device__ __align__(16) float g_enc[BT*HH];
__device__ __align__(16) float g_hbuf[2*BB*HH];
__device__ __align__(16) float g_xg_pos[BT*G4P];
__device__ __align__(16) float g_mu[BT];
__device__ __align__(16) float g_sg[BT];
__device__ __align__(16) float g_gw[(size_t)BB*TT*TT];
__device__ __align__(16) float g_cat[(size_t)BT*2*HH];        // [ctx | enc]
__device__ __align__(16) float g_bias_enc[G4H];
__device__ __align__(16) float g_bias_pos[G4P];
__device__ unsigned g_bar;
// split-fp16 operands for HMMA GEMMs (2-term: A needs hi+lo, B needs hi only)
__device__ __align__(16) __half g_embA_hi[BT*HH];
__device__ __align__(16) __half g_embA_lo[BT*HH];
__device__ __align__(16) __half g_wih_hi[G4H*HH];
__device__ __align__(16) __half g_cat_hi[(size_t)BT*2*HH];
__device__ __align__(16) __half g_cat_lo[(size_t)BT*2*HH];
__device__ __align__(16) __half g_wcat_hi[HH*2*HH];
__device__ __align__(16) __half g_comb_hi[BT*HH];
__device__ __align__(16) __half g_comb_lo[BT*HH];
__device__ __align__(16) __half g_emb_hi[(size_t)VV*HH];

__device__ __forceinline__ float sigf(float x) { return 1.f / (1.f + expf(-x)); }

#define FMA2(acc, a, b) asm("fma.rn.f32x2 %0, %1, %2, %0;" : "+l"(acc) : "l"(a), "l"(b))

// mma.sync m16n8k16 fp16->fp32 (baseline PTX, sm_80+; fragment layout identical to bf16)
#define MMA_F16(c, a, b0, b1)                                               \
    asm volatile("mma.sync.aligned.m16n8k16.row.col.f32.f16.f16.f32 "       \
        "{%0,%1,%2,%3}, {%4,%5,%6,%7}, {%8,%9}, {%0,%1,%2,%3};"             \
        : "+f"((c)[0]), "+f"((c)[1]), "+f"((c)[2]), "+f"((c)[3])            \
        : "r"((a)[0]), "r"((a)[1]), "r"((a)[2]), "r"((a)[3]),               \
          "r"(b0), "r"(b1))

// cp.async (baseline PTX, sm_80+)
#define CP_ASYNC16(saddr, gptr)                                             \
    asm volatile("cp.async.cg.shared.global [%0], [%1], 16;"                \
        :: "r"(saddr), "l"(gptr) : "memory")
#define CP_COMMIT() asm volatile("cp.async.commit_group;" ::: "memory")
#define CP_WAIT1()  asm volatile("cp.async.wait_group 1;" ::: "memory")
#define CP_WAIT0()  asm volatile("cp.async.wait_group 0;" ::: "memory")

// ------------------------- reset (per replay: barrier + h0) -------------------------
__global__ void reset_kernel() {
    int i = blockIdx.x * blockDim.x + threadIdx.x;
    if (i == 0) g_bar = 0u;
    if (i < BB * HH) g_hbuf[i] = 0.f;
}

// ------------------------- combined biases -------------------------
__global__ void bias_kernel(const float* __restrict__ bih, const float* __restrict__ bhh,
                            const float* __restrict__ pbih, const float* __restrict__ pbhh) {
    int i = blockIdx.x * blockDim.x + threadIdx.x;
    if (i < G4H) g_bias_enc[i] = bih[i] + bhh[i];
    if (i < G4P) g_bias_pos[i] = pbih[i] + pbhh[i];
}

// ------------------------- embedding gather fused with fp16 hi/lo split -------------------------
__global__ void gather_split_kernel(const int* __restrict__ tokens, const float* __restrict__ emb) {
    int i = blockIdx.x * blockDim.x + threadIdx.x;      // float4 index
    if (i >= BT * (HH / 4)) return;
    int r = i >> 7, c4 = i & 127;
    int tok = tokens[r];
    float4 v = ((const float4*)(emb + (size_t)tok * HH))[c4];
    __half h0 = __float2half(v.x), h1 = __float2half(v.y);
    __half h2 = __float2half(v.z), h3 = __float2half(v.w);
    __half l0 = __float2half(v.x - __half2float(h0));
    __half l1 = __float2half(v.y - __half2float(h1));
    __half l2 = __float2half(v.z - __half2float(h2));
    __half l3 = __float2half(v.w - __half2float(h3));
    size_t o = (size_t)r * HH + (size_t)c4 * 4;
    *(__half2*)(g_embA_hi + o)     = __halves2half2(h0, h1);
    *(__half2*)(g_embA_hi + o + 2) = __halves2half2(h2, h3);
    *(__half2*)(g_embA_lo + o)     = __halves2half2(l0, l1);
    *(__half2*)(g_embA_lo + o + 2) = __halves2half2(l2, l3);
}

// ------------------------- enc -> g_cat[:, HH:2HH] copy -------------------------
__global__ void enccat_kernel() {
    int i = blockIdx.x * blockDim.x + threadIdx.x;      // float4 index over BT*HH/4
    if (i >= BT * (HH / 4)) return;
    int row = i >> 7, c4 = i & 127;
    ((float4*)g_cat)[(size_t)row * (2 * HH / 4) + (HH / 4) + c4] = ((const float4*)g_enc)[i];
}

// ------------------------- fp32 -> fp16 hi only (B operands) -------------------------
__global__ void split_h_kernel(const float* __restrict__ src, __half* __restrict__ hi, long long n) {
    long long i = (long long)blockIdx.x * blockDim.x + threadIdx.x;
    if (i >= n) return;
    hi[i] = __float2half(src[i]);
}

// ------------------------- fp32 -> fp16 hi/lo (A operands) -------------------------
__global__ void split_hl_kernel(const float* __restrict__ src, __half* __restrict__ hi,
                                __half* __restrict__ lo, long long n) {
    long long i = (long long)blockIdx.x * blockDim.x + threadIdx.x;
    if (i >= n) return;
    float x = src[i];
    __half h = __float2half(x);
    hi[i] = h;
    lo[i] = __float2half(x - __half2float(h));
}

// ------------------------- fp32 SGEMM, double-buffered, f32x2-packed FMA -------------------------
// C = A[M,K] * op(B) (+bias). Used only for ctx (non-trans) and xg_pos (N=80).
template <bool TRANSB>
__global__ void __launch_bounds__(256)
sgemm_kernel(const float* __restrict__ A, int lda, long long sA,
             const float* __restrict__ B, int ldb, long long sB,
             float* __restrict__ C, int ldc, long long sC,
             int M, int N, int K,
             const float* __restrict__ bias, int act, float beta) {
    constexpr int BM = 128, BN = 128, BK = 8;
    __shared__ float As[2][BK][BM + 4];
    __shared__ float Bs[2][BK][BN + 4];

    A += (size_t)blockIdx.z * sA;
    B += (size_t)blockIdx.z * sB;
    C += (size_t)blockIdx.z * sC;

    const int bRow = blockIdx.y * BM;
    const int bCol = blockIdx.x * BN;
    const int tid = threadIdx.x;

    const int aRow = tid >> 1, aK = (tid & 1) * 4;
    const int tRow = (tid / 16) * 8, tCol = (tid % 16) * 8;
    const int bN  = tid >> 1, bKk = (tid & 1) * 4;
    const int bKr = tid >> 5, bN4 = (tid & 31) * 4;

    unsigned long long acc2[8][4];
#pragma unroll
    for (int i = 0; i < 8; i++)
#pragma unroll
        for (int j2 = 0; j2 < 4; j2++) acc2[i][j2] = 0ull;

    auto fetchA = [&](int kt) {
        return *(const float4*)(A + (size_t)(bRow + aRow) * lda + kt + aK);
    };
    auto fetchB = [&](int kt) {
        float4 bv = make_float4(0.f, 0.f, 0.f, 0.f);
        if (TRANSB) {
            if (bCol + bN < N)
                bv = *(const float4*)(B + (size_t)(bCol + bN) * ldb + kt + bKk);
        } else {
            if (bCol + bN4 < N)
                bv = *(const float4*)(B + (size_t)(kt + bKr) * ldb + bCol + bN4);
        }
        return bv;
    };
    auto commit = [&](int buf, float4 av, float4 bv) {
        As[buf][aK + 0][aRow] = av.x; As[buf][aK + 1][aRow] = av.y;
        As[buf][aK + 2][aRow] = av.z; As[buf][aK + 3][aRow] = av.w;
        if (TRANSB) {
            Bs[buf][bKk + 0][bN] = bv.x; Bs[buf][bKk + 1][bN] = bv.y;
            Bs[buf][bKk + 2][bN] = bv.z; Bs[buf][bKk + 3][bN] = bv.w;
        } else {
            Bs[buf][bKr][bN4 + 0] = bv.x; Bs[buf][bKr][bN4 + 1] = bv.y;
            Bs[buf][bKr][bN4 + 2] = bv.z; Bs[buf][bKr][bN4 + 3] = bv.w;
        }
    };

    {
        float4 av = fetchA(0), bv = fetchB(0);
        commit(0, av, bv);
    }
    __syncthreads();

    const int nTiles = K / BK;
    int buf = 0;
    for (int tile = 0; tile < nTiles; tile++) {
        float4 av, bv;
        if (tile + 1 < nTiles) {
            av = fetchA((tile + 1) * BK);
            bv = fetchB((tile + 1) * BK);
        }
#pragma unroll
        for (int kk = 0; kk < BK; kk++) {
            float4 ra0 = *(const float4*)&As[buf][kk][tRow];
            float4 ra1 = *(const float4*)&As[buf][kk][tRow + 4];
            float ra[8] = {ra0.x, ra0.y, ra0.z, ra0.w, ra1.x, ra1.y, ra1.z, ra1.w};
            unsigned long long apair[8];
#pragma unroll
            for (int i = 0; i < 8; i++)
                asm("mov.b64 %0, {%1, %1};" : "=l"(apair[i]) : "f"(ra[i]));
            const unsigned long long* bp =
                (const unsigned long long*)&Bs[buf][kk][tCol];
            unsigned long long bpair[4];
#pragma unroll
            for (int j2 = 0; j2 < 4; j2++) bpair[j2] = bp[j2];
#pragma unroll
            for (int i = 0; i < 8; i++)
#pragma unroll
                for (int j2 = 0; j2 < 4; j2++)
                    FMA2(acc2[i][j2], apair[i], bpair[j2]);
        }
        if (tile + 1 < nTiles) {
            commit(buf ^ 1, av, bv);
            __syncthreads();
            buf ^= 1;
        }
    }

    float acc[8][8];
#pragma unroll
    for (int i = 0; i < 8; i++)
#pragma unroll
        for (int j2 = 0; j2 < 4; j2++)
            asm("mov.b64 {%0, %1}, %2;"
                : "=f"(acc[i][2 * j2]), "=f"(acc[i][2 * j2 + 1])
                : "l"(acc2[i][j2]));

    const bool fullTile = (bCol + BN <= N);
    if (fullTile && beta == 0.f && act == 0) {
#pragma unroll
        for (int i = 0; i < 8; i++) {
            size_t rowOff = (size_t)(bRow + tRow + i) * ldc + bCol + tCol;
#pragma unroll
            for (int j4 = 0; j4 < 2; j4++) {
                float4 v = make_float4(acc[i][j4 * 4 + 0], acc[i][j4 * 4 + 1],
                                       acc[i][j4 * 4 + 2], acc[i][j4 * 4 + 3]);
                if (bias) {
                    int col = bCol + tCol + j4 * 4;
                    v.x += bias[col + 0]; v.y += bias[col + 1];
                    v.z += bias[col + 2]; v.w += bias[col + 3];
                }
                *(float4*)(C + rowOff + j4 * 4) = v;
            }
        }
    } else {
#pragma unroll
        for (int i = 0; i < 8; i++) {
            int row = bRow + tRow + i;
#pragma unroll
            for (int j = 0; j < 8; j++) {
                int col = bCol + tCol + j;
                if (col < N) {
                    float v = acc[i][j];
                    if (beta != 0.f) v += beta * C[(size_t)row * ldc + col];
                    if (bias) v += bias[col];
                    if (act == 1) v = tanhf(v);
                    C[(size_t)row * ldc + col] = v;
                }
            }
        }
    }
}

// ------------------------- HMMA split-fp16 GEMM (2-term, cp.async pipelined) ----------------
// out[M, N] = A @ B^T (+bias)(tanh), A approx by (Ah + Al), B by Bh (hi only):
//   acc = Ah*Bh + Al*Bh = (Ah+Al)*Bh ~= A*Bh  (error = A*Bl ~ 2^-12, fp32 accum).
// A: [M, K] fp16 hi/lo row-major (lda=K). B: [N, K] fp16 hi row-major (ldb=K) = .col operand.
// Block 128x128, BK=32, 256 thr = 8 warps, warp tile 32(M) x 64(N).
// 2-stage cp.async pipeline, 3 tiles/stage (Ah, Al, Bh), 60 KB dyn smem, 2 CTAs/SM.
// Output: fp32 (out!=null) or fused fp16 hi/lo split (ohi/olo). N,M mult of 128, K mult of 32.
#define MM_LDS 40   /* 32 + 8 pad fp16; frag-LDS bank = (20g+t4)%32, all 32 distinct */
#define MM_TILE (128 * MM_LDS)          /* fp16 per tile  */
#define MM_STAGE (3 * MM_TILE)          /* fp16 per stage */
#define SMEM_MM (2 * MM_STAGE * 2)      /* bytes          */

__device__ __forceinline__ void mm_load_async(uint32_t dst, const __half* src,
                                              int row0, int col0, int ld, int tid) {
    // 128 rows x 32 fp16 = 512 x 16B chunks; 2 per thread
#pragma unroll
    for (int it = 0; it < 2; it++) {
        int idx = tid + it * 256;
        int r = idx >> 2, c4 = idx & 3;
        const __half* g = src + (size_t)(row0 + r) * ld + col0 + c4 * 8;
        CP_ASYNC16(dst + (uint32_t)(r * MM_LDS + c4 * 8) * 2, g);
    }
}

__global__ void __launch_bounds__(256, 2)
mma_gemm_kernel(const __half* __restrict__ Ah, const __half* __restrict__ Al,
                const __half* __restrict__ Bh,
                int K, const float* __restrict__ bias, int act,
                float* __restrict__ out, __half* __restrict__ ohi, __half* __restrict__ olo,
                int ldc) {
    extern __shared__ __half dyn[];
    const uint32_t sbase = (uint32_t)__cvta_generic_to_shared(dyn);

    const int tid = threadIdx.x;
    const int w = tid >> 5, lane = tid & 31;
    const int g = lane >> 2, t4 = lane & 3;
    const int wm = w & 3, wn = w >> 2;           // 4 M-warps x 2 N-warps
    const int n0 = blockIdx.x * 128, m0 = blockIdx.y * 128;

    float acc[2][8][4];
#pragma unroll
    for (int mt = 0; mt < 2; mt++)
#pragma unroll
        for (int nt = 0; nt < 8; nt++)
#pragma unroll
            for (int q = 0; q < 4; q++) acc[mt][nt][q] = 0.f;

    auto issue_chunk = [&](int kc, int st) {
        uint32_t sb = sbase + (uint32_t)(st * MM_STAGE) * 2;
        mm_load_async(sb + 0u * MM_TILE * 2, Ah, m0, kc, K, tid);
        mm_load_async(sb + 1u * MM_TILE * 2, Al, m0, kc, K, tid);
        mm_load_async(sb + 2u * MM_TILE * 2, Bh, n0, kc, K, tid);
        CP_COMMIT();
    };

    const int nChunks = K / 32;
    issue_chunk(0, 0);

    for (int c = 0; c < nChunks; c++) {
        const int st = c & 1;
        if (c + 1 < nChunks) {
            issue_chunk((c + 1) * 32, st ^ 1);
            CP_WAIT1();                 // chunk c landed; chunk c+1 may be in flight
        } else {
            CP_WAIT0();
        }
        __syncthreads();

        const __half* sAh = dyn + st * MM_STAGE + 0 * MM_TILE;
        const __half* sAl = dyn + st * MM_STAGE + 1 * MM_TILE;
        const __half* sBh = dyn + st * MM_STAGE + 2 * MM_TILE;
#pragma unroll
        for (int ks = 0; ks < 2; ks++) {
            const int kb = ks * 16 + t4 * 2;
            uint32_t ahf[2][4], alf[2][4];
#pragma unroll
            for (int mt = 0; mt < 2; mt++) {
                int r0 = (wm * 32 + mt * 16 + g) * MM_LDS + kb;
                ahf[mt][0] = *(const uint32_t*)&sAh[r0];
                ahf[mt][1] = *(const uint32_t*)&sAh[r0 + 8 * MM_LDS];
                ahf[mt][2] = *(const uint32_t*)&sAh[r0 + 8];
                ahf[mt][3] = *(const uint32_t*)&sAh[r0 + 8 * MM_LDS + 8];
                alf[mt][0] = *(const uint32_t*)&sAl[r0];
                alf[mt][1] = *(const uint32_t*)&sAl[r0 + 8 * MM_LDS];
                alf[mt][2] = *(const uint32_t*)&sAl[r0 + 8];
                alf[mt][3] = *(const uint32_t*)&sAl[r0 + 8 * MM_LDS + 8];
            }
#pragma unroll
            for (int nt = 0; nt < 8; nt++) {
                int nr = (wn * 64 + nt * 8 + g) * MM_LDS + kb;
                uint32_t bh0 = *(const uint32_t*)&sBh[nr];
                uint32_t bh1 = *(const uint32_t*)&sBh[nr + 8];
#pragma unroll
                for (int mt = 0; mt < 2; mt++) {
                    MMA_F16(acc[mt][nt], ahf[mt], bh0, bh1);
                    MMA_F16(acc[mt][nt], alf[mt], bh0, bh1);
                }
            }
        }
        __syncthreads();   // all reads of stage st done before it is refilled (c+2)
    }

    // epilogue: c0,c1 -> (row, col..col+1); c2,c3 -> (row+8, col..col+1)
#pragma unroll
    for (int mt = 0; mt < 2; mt++) {
#pragma unroll
        for (int nt = 0; nt < 8; nt++) {
            int row = m0 + wm * 32 + mt * 16 + g;
            int col = n0 + wn * 64 + nt * 8 + t4 * 2;
            float b0 = bias[col], b1 = bias[col + 1];
            float v0 = acc[mt][nt][0] + b0, v1 = acc[mt][nt][1] + b1;
            float v2 = acc[mt][nt][2] + b0, v3 = acc[mt][nt][3] + b1;
            if (act == 1) {
                v0 = tanhf(v0); v1 = tanhf(v1);
                v2 = tanhf(v2); v3 = tanhf(v3);
            }
            if (ohi) {
                // fused fp16 hi/lo split output
                __half h0 = __float2half(v0), h1 = __float2half(v1);
                __half h2 = __float2half(v2), h3 = __float2half(v3);
                *(__half2*)(ohi + (size_t)row * ldc + col) = __halves2half2(h0, h1);
                *(__half2*)(ohi + (size_t)(row + 8) * ldc + col) = __halves2half2(h2, h3);
                *(__half2*)(olo + (size_t)row * ldc + col) = __halves2half2(
                    __float2half(v0 - __half2float(h0)), __float2half(v1 - __half2float(h1)));
                *(__half2*)(olo + (size_t)(row + 8) * ldc + col) = __halves2half2(
                    __float2half(v2 - __half2float(h2)), __float2half(v3 - __half2float(h3)));
            } else {
                *(float2*)(out + (size_t)row * ldc + col) = make_float2(v0, v1);
                *(float2*)(out + (size_t)(row + 8) * ldc + col) = make_float2(v2, v3);
            }
        }
    }
}

// ------------------------- persistent encoder LSTM (register-stationary weights) -----------
__global__ void __launch_bounds__(128)
enc_lstm_kernel(const float* __restrict__ Whh) {
    __shared__ float h_sm[8 * 544];
    __shared__ float part_sm[16 * 64];
    __shared__ float gate_sm[128];

    const int tid = threadIdx.x;
    const int r  = tid >> 3;
    const int ks = tid & 7;
    const int k0 = blockIdx.x * 4;
    const int jg = (r >> 2) * HH + k0 + (r & 3);

    unsigned long long wreg[32];
    {
        const ulonglong2* wr = (const ulonglong2*)(Whh + (size_t)jg * HH + ks * 64);
#pragma unroll
        for (int m = 0; m < 16; m++) {
            ulonglong2 v = wr[m];
            wreg[2 * m] = v.x; wreg[2 * m + 1] = v.y;
        }
    }
    const ulonglong2* hptr[8];
#pragma unroll
    for (int b = 0; b < 8; b++)
        hptr[b] = (const ulonglong2*)&h_sm[b * 544 + ks * 68];

    float c = 0.f;

    for (int t = 0; t < TT; t++) {
        const int cur = t & 1;
        const float4* hg = (const float4*)(g_hbuf + cur * (BB * HH));
        for (int i = tid; i < BB * HH / 4; i += 128) {
            float4 v = __ldcg(hg + i);
            int bb = i >> 7, k4 = i & 127;
            *(float4*)&h_sm[bb * 544 + (k4 >> 4) * 68 + (k4 & 15) * 4] = v;
        }
        float xgv = __ldg(&g_xg_enc[(size_t)(ks * TT + t) * G4H + jg]);
        __syncthreads();

        unsigned long long acc[8];
#pragma unroll
        for (int b = 0; b < 8; b++) acc[b] = 0ull;
#pragma unroll
        for (int m = 0; m < 16; m++) {
            ulonglong2 hv[8];
#pragma unroll
            for (int b = 0; b < 8; b++) hv[b] = hptr[b][m];
#pragma unroll
            for (int b = 0; b < 8; b++) FMA2(acc[b], wreg[2 * m], hv[b].x);
#pragma unroll
            for (int b = 0; b < 8; b++) FMA2(acc[b], wreg[2 * m + 1], hv[b].y);
        }
#pragma unroll
        for (int b = 0; b < 8; b++) {
            float lo, hi;
            asm("mov.b64 {%0, %1}, %2;" : "=f"(lo), "=f"(hi) : "l"(acc[b]));
            part_sm[r * 64 + b * 8 + ks] = lo + hi;
        }
        __syncthreads();

        {
            float s = xgv;
            const float* pp = &part_sm[r * 64 + ks * 8];
#pragma unroll
            for (int q = 0; q < 8; q++) s += pp[q];
            gate_sm[r * 8 + ks] = s;
        }
        __syncthreads();

        if (tid < 32) {
            int kl = tid >> 3, b2 = tid & 7;
            float iv = gate_sm[(0 + kl) * 8 + b2];
            float fv = gate_sm[(4 + kl) * 8 + b2];
            float gv = gate_sm[(8 + kl) * 8 + b2];
            float ov = gate_sm[(12 + kl) * 8 + b2];
            c = sigf(fv) * c + sigf(iv) * tanhf(gv);
            float h = sigf(ov) * tanhf(c);
            int nxt = cur ^ 1;
            g_hbuf[nxt * (BB * HH) + b2 * HH + k0 + kl] = h;
            g_enc[(size_t)(b2 * TT + t) * HH + k0 + kl] = h;
            __threadfence();
        }
        __syncthreads();
        if (tid == 0) {
            __threadfence();
            atomicAdd(&g_bar, 1u);
            unsigned tgt = (unsigned)(t + 1) * gridDim.x;
            volatile unsigned* vb = &g_bar;
            while (*vb < tgt) { }
        }
        __syncthreads();
    }
}

// ------------------------- positional LSTM + mu/sg scan (one block per batch) -------------------------
__global__ void __launch_bounds__(128)
pos_lstm_kernel(const float* __restrict__ Whh, const float* __restrict__ W_mu,
                const float* __restrict__ b_mu, const float* __restrict__ W_sig,
                const float* __restrict__ b_sig, const int* __restrict__ pad_lengths) {
    __shared__ float wp[G4P * PP];
    __shared__ float hp[PP];
    __shared__ float gate_sm[G4P];
    __shared__ float mwsg[4];

    const int b = blockIdx.x;
    const int tid = threadIdx.x;
    const float L = (float)pad_lengths[b];

    for (int i = tid; i < G4P * PP; i += 128) wp[i] = Whh[i];
    if (tid < PP) hp[tid] = 0.f;
    float c = 0.f;
    float mu_prev = 0.f;
    __syncthreads();

    for (int t = 0; t < TT; t++) {
        if (tid < G4P) {
            float g = g_xg_pos[(size_t)(b * TT + t) * G4P + tid];
            const float* wr = &wp[tid * PP];
#pragma unroll
            for (int k = 0; k < PP; k++) g += hp[k] * wr[k];
            gate_sm[tid] = g;
        }
        __syncthreads();
        if (tid < PP) {
            float iv = gate_sm[tid], fv = gate_sm[PP + tid];
            float gv = gate_sm[2 * PP + tid], ov = gate_sm[3 * PP + tid];
            c = sigf(fv) * c + sigf(iv) * tanhf(gv);
            float h = sigf(ov) * tanhf(c);
            hp[tid] = h;
        }
        __syncthreads();
        if (tid < 4) {
            float s = 0.f;
            if (tid < 3) {
#pragma unroll
                for (int k = 0; k < PP; k++) s += hp[k] * W_mu[tid * PP + k];
                mwsg[tid] = fmaxf(s + b_mu[tid], 0.f);
            } else {
#pragma unroll
                for (int k = 0; k < PP; k++) s += hp[k] * W_sig[k];
                float sgv = sigf(s + b_sig[0]);
                mwsg[3] = sgv;
                g_sg[b * TT + t] = sgv;
            }
        }
        __syncthreads();
        if (tid == 0) {
            float tf = (float)t;
            float mu = mwsg[0] * mu_prev + mwsg[1] / L + mwsg[2] * (tf + 1.f) / L;
            mu = fmaxf(mu, tf / L);
            mu_prev = mu;
            g_mu[b * TT + t] = mu;
        }
        __syncthreads();
    }
}

// ------------------------- attention weights (gaussian, causal, L1-normalized) -------------------------
__global__ void __launch_bounds__(128)
attn_w_kernel(const int* __restrict__ pad_lengths) {
    const int tq = blockIdx.x;
    const int b = blockIdx.y;
    const int tid = threadIdx.x;
    __shared__ float red[5];

    const float mu = g_mu[b * TT + tq];
    const float s = g_sg[b * TT + tq];
    const float inv_den = 1.f / (2.f * s * s + 0.001f);
    const float L = (float)pad_lengths[b];

    float e[4];
    float sum = 0.f;
#pragma unroll
    for (int u = 0; u < 4; u++) {
        int tk = tid + u * 128;
        float v = 0.f;
        if (tk <= tq) {
            float d = (float)tk / L - mu;
            v = expf(-d * d * inv_den);
        }
        e[u] = v;
        sum += v;
    }
#pragma unroll
    for (int off = 16; off; off >>= 1) sum += __shfl_down_sync(0xffffffffu, sum, off);
    if ((tid & 31) == 0) red[tid >> 5] = sum;
    __syncthreads();
    if (tid == 0) red[4] = 1.f / fmaxf(red[0] + red[1] + red[2] + red[3], 1e-12f);
    __syncthreads();
    float inv = red[4];
    float* row = &g_gw[((size_t)b * TT + tq) * TT];
#pragma unroll
    for (int u = 0; u < 4; u++) row[tid + u * 128] = e[u] * inv;
}

// ------------------------- host -------------------------
extern "C" void kernel_launch(void* const* d_in, const int* in_sizes, int n_in,
                              void* d_out, int out_size) {
    const int*   tokens      = (const int*)d_in[0];
    const int*   pad_lengths = (const int*)d_in[1];
    const float* embedding   = (const float*)d_in[2];
    const float* enc_Wih     = (const float*)d_in[3];
    const float* enc_Whh     = (const float*)d_in[4];
    const float* enc_bih     = (const float*)d_in[5];
    const float* enc_bhh     = (const float*)d_in[6];
    const float* pos_Wih     = (const float*)d_in[7];
    const float* pos_Whh     = (const float*)d_in[8];
    const float* pos_bih     = (const float*)d_in[9];
    const float* pos_bhh     = (const float*)d_in[10];
    const float* W_mu        = (const float*)d_in[11];
    const float* b_mu        = (const float*)d_in[12];
    const float* W_sig       = (const float*)d_in[13];
    const float* b_sig       = (const float*)d_in[14];
    const float* W_cat       = (const float*)d_in[15];
    const float* b_cat       = (const float*)d_in[16];
    const float* dec_b       = (const float*)d_in[17];
    float* out = (float*)d_out;

    float *p_xg_enc, *p_enc, *p_xg_pos, *p_gw, *p_cat, *p_benc, *p_bpos;
    __half *p_eAhi, *p_eAlo, *p_wihhi, *p_cathi, *p_catlo, *p_wcathi, *p_chi, *p_clo, *p_ehi;
    cudaGetSymbolAddress((void**)&p_xg_enc, g_xg_enc);
    cudaGetSymbolAddress((void**)&p_enc,    g_enc);
    cudaGetSymbolAddress((void**)&p_xg_pos, g_xg_pos);
    cudaGetSymbolAddress((void**)&p_gw,     g_gw);
    cudaGetSymbolAddress((void**)&p_cat,    g_cat);
    cudaGetSymbolAddress((void**)&p_benc,   g_bias_enc);
    cudaGetSymbolAddress((void**)&p_bpos,   g_bias_pos);
    cudaGetSymbolAddress((void**)&p_eAhi,   g_embA_hi);
    cudaGetSymbolAddress((void**)&p_eAlo,   g_embA_lo);
    cudaGetSymbolAddress((void**)&p_wihhi,  g_wih_hi);
    cudaGetSymbolAddress((void**)&p_cathi,  g_cat_hi);
    cudaGetSymbolAddress((void**)&p_catlo,  g_cat_lo);
    cudaGetSymbolAddress((void**)&p_wcathi, g_wcat_hi);
    cudaGetSymbolAddress((void**)&p_chi,    g_comb_hi);
    cudaGetSymbolAddress((void**)&p_clo,    g_comb_lo);
    cudaGetSymbolAddress((void**)&p_ehi,    g_emb_hi);

    cudaFuncSetAttribute(mma_gemm_kernel,
                         cudaFuncAttributeMaxDynamicSharedMemorySize, SMEM_MM);

    // 1. reset barrier + h0
    reset_kernel<<<16, 256>>>();
    // 2. combined biases
    bias_kernel<<<8, 256>>>(enc_bih, enc_bhh, pos_bih, pos_bhh);
    // 3. embedding gather fused with fp16 split (embA hi/lo)
    gather_split_kernel<<<(BT * (HH / 4) + 255) / 256, 256>>>(tokens, embedding);
    // 4. Wih -> fp16 hi
    split_h_kernel<<<(unsigned)(((long long)G4H * HH + 255) / 256), 256>>>(
        enc_Wih, p_wihhi, (long long)G4H * HH);
    // 5. xg_enc = embA @ enc_Wih^T + (bih+bhh)  [4096 x 2048], HMMA 2-term
    mma_gemm_kernel<<<dim3(G4H / 128, BT / 128, 1), 256, SMEM_MM>>>(
        p_eAhi, p_eAlo, p_wihhi, HH, p_benc, 0, p_xg_enc, nullptr, nullptr, G4H);
    // 6. encoder LSTM (persistent, grid barrier, register-stationary weights)
    enc_lstm_kernel<<<128, 128>>>(enc_Whh);
    // 7. emb -> fp16 hi (decoder B operand)
    split_h_kernel<<<(unsigned)(((long long)VV * HH + 255) / 256), 256>>>(
        embedding, p_ehi, (long long)VV * HH);
    // 8. W_cat -> fp16 hi
    split_h_kernel<<<(unsigned)(((long long)HH * 2 * HH + 255) / 256), 256>>>(
        W_cat, p_wcathi, (long long)HH * 2 * HH);
    // 9. xg_pos = enc @ pos_Wih^T + (pbih+pbhh)  [4096 x 80], fp32 (N=80)
    sgemm_kernel<true><<<dim3(1, BT / 128, 1), 256>>>(
        p_enc, HH, 0, pos_Wih, HH, 0, p_xg_pos, G4P, 0,
        BT, G4P, HH, p_bpos, 0, 0.f);
    // 10. positional LSTM + mu/sg scan
    pos_lstm_kernel<<<BB, 128>>>(pos_Whh, W_mu, b_mu, W_sig, b_sig, pad_lengths);
    // 11. attention weights
    attn_w_kernel<<<dim3(TT, BB, 1), 128>>>(pad_lengths);
    // 12. ctx[b] = g[b] @ enc[b] into g_cat[:, 0:512] (ldc=1024); enc copy into [:, 512:1024]
    sgemm_kernel<false><<<dim3(HH / 128, TT / 128, BB), 256>>>(
        p_gw, TT, (long long)TT * TT, p_enc, HH, (long long)TT * HH,
        p_cat, 2 * HH, (long long)TT * 2 * HH,
        TT, HH, TT, nullptr, 0, 0.f);
    enccat_kernel<<<(BT * (HH / 4) + 255) / 256, 256>>>();
    // 13. cat -> fp16 hi/lo
    split_hl_kernel<<<(unsigned)(((long long)BT * 2 * HH + 255) / 256), 256>>>(
        p_cat, p_cathi, p_catlo, (long long)BT * 2 * HH);
    // 14. comb = tanh([ctx,enc] @ W_cat^T + b_cat)  [4096 x 512], K=1024, HMMA 2-term
    //     output fused-split directly to fp16 hi/lo (decoder A operand)
    mma_gemm_kernel<<<dim3(HH / 128, BT / 128, 1), 256, SMEM_MM>>>(
        p_cathi, p_catlo, p_wcathi, 2 * HH, b_cat, 1, nullptr, p_chi, p_clo, HH);
    // 15. logits = comb @ embedding^T + dec_b  [4096 x 32000], HMMA 2-term
    mma_gemm_kernel<<<dim3(VV / 128, BT / 128, 1), 256, SMEM_MM>>>(
        p_chi, p_clo, p_ehi, HH, dec_b, 0, out, nullptr, nullptr, VV);

    (void)in_sizes; (void)n_in; (void)out_size;
}